// round 3
// baseline (speedup 1.0000x reference)
#include <cuda_runtime.h>
#include <cuda_bf16.h>
#include <cstdint>

#define N_MAX 50000
#define HID 64

// Scratch (device globals; never referenced from host code)
__device__ int   g_deg[N_MAX];
__device__ float g_dinv[N_MAX];
__device__ __align__(16) float g_A[N_MAX * HID];   // GEMM output h
__device__ __align__(16) float g_B[N_MAX * HID];   // aggregation buffer
__device__ __align__(16) float g_C[N_MAX * HID];   // layer activation

// Device-side buffer selector: 0 = g_A, 1 = g_B, 2 = g_C
__device__ __forceinline__ float* buf_sel(int id) {
    return (id == 0) ? g_A : (id == 1) ? g_B : g_C;
}

// ---------------- degree / dinv ----------------
__global__ void zero_deg_kernel(int n) {
    int i = blockIdx.x * blockDim.x + threadIdx.x;
    if (i < n) g_deg[i] = 0;
}

__global__ void count_deg_kernel(const int* __restrict__ dst, int E) {
    int i = blockIdx.x * blockDim.x + threadIdx.x;
    if (i < E) atomicAdd(&g_deg[dst[i]], 1);
}

__global__ void dinv_kernel(int n) {
    int i = blockIdx.x * blockDim.x + threadIdx.x;
    if (i < n) g_dinv[i] = rsqrtf((float)g_deg[i] + 1.0f);  // +1 self loop, always > 0
}

// ---------------- GEMM: H[n,C] = X[n,K] @ W[K,C] ----------------
// X: external pointer if x_ext != nullptr, else internal buffer x_sel.
// Output always goes to internal buffer g_A.
template<int K, int C, int TY, int RPT>
__global__ void gemm_kernel(const float* __restrict__ x_ext, int x_sel,
                            const float* __restrict__ W, int n) {
    const float* X = x_ext ? x_ext : buf_sel(x_sel);
    float* H = g_A;
    constexpr int BR = TY * RPT;
    __shared__ __align__(16) float Ws[K * C];
    __shared__ __align__(16) float Xs[BR][K];
    const int tid = threadIdx.y * C + threadIdx.x;
    const int nthreads = C * TY;
    for (int i = tid; i < K * C; i += nthreads) Ws[i] = W[i];
    const int rowBlock = blockIdx.x * BR;
    for (int i = tid; i < BR * K; i += nthreads) {
        int r = i / K, k = i % K;
        int row = rowBlock + r;
        Xs[r][k] = (row < n) ? X[(size_t)row * K + k] : 0.0f;
    }
    __syncthreads();

    const int col = threadIdx.x;
    const int r0 = threadIdx.y * RPT;
    float acc[RPT];
#pragma unroll
    for (int r = 0; r < RPT; r++) acc[r] = 0.0f;

#pragma unroll 4
    for (int k = 0; k < K; k += 4) {
        float w0 = Ws[(k + 0) * C + col];
        float w1 = Ws[(k + 1) * C + col];
        float w2 = Ws[(k + 2) * C + col];
        float w3 = Ws[(k + 3) * C + col];
#pragma unroll
        for (int r = 0; r < RPT; r++) {
            float4 xv = *reinterpret_cast<const float4*>(&Xs[r0 + r][k]);
            acc[r] = fmaf(xv.x, w0, acc[r]);
            acc[r] = fmaf(xv.y, w1, acc[r]);
            acc[r] = fmaf(xv.z, w2, acc[r]);
            acc[r] = fmaf(xv.w, w3, acc[r]);
        }
    }
#pragma unroll
    for (int r = 0; r < RPT; r++) {
        int row = rowBlock + r0 + r;
        if (row < n) H[(size_t)row * C + col] = acc[r];
    }
}

// ---------------- self-loop init: g_B = g_A * dinv^2 ----------------
template<int C>
__global__ void init_self_kernel(int n) {
    long long idx = (long long)blockIdx.x * blockDim.x + threadIdx.x;  // quad index
    long long total = (long long)n * (C / 4);
    if (idx >= total) return;
    long long base = idx * 4;
    int node = (int)(base / C);
    float dv = g_dinv[node];
    float s = dv * dv;
    float4 hv = *reinterpret_cast<const float4*>(&g_A[base]);
    float4 o;
    o.x = hv.x * s; o.y = hv.y * s; o.z = hv.z * s; o.w = hv.w * s;
    *reinterpret_cast<float4*>(&g_B[base]) = o;
}

// ---------------- edge aggregation: g_B += scatter(norm * g_A[src]) ----------------
template<int C>
__global__ void edge_aggregate_kernel(const int* __restrict__ src,
                                      const int* __restrict__ dst, int E) {
    constexpr int Q = C / 4;
    long long idx = (long long)blockIdx.x * blockDim.x + threadIdx.x;
    if (idx >= (long long)E * Q) return;
    int e = (int)(idx / Q);
    int q = (int)(idx % Q);
    int s = src[e];
    int d = dst[e];
    float norm = g_dinv[s] * g_dinv[d];
    float4 hv = *reinterpret_cast<const float4*>(&g_A[(size_t)s * C + q * 4]);
    float* ap = &g_B[(size_t)d * C + q * 4];
    atomicAdd(ap + 0, hv.x * norm);
    atomicAdd(ap + 1, hv.y * norm);
    atomicAdd(ap + 2, hv.z * norm);
    atomicAdd(ap + 3, hv.w * norm);
}

// ---------------- post: bias (+ BN + ReLU); src = g_B, dst = out_ext or g_C ----------------
template<int C, bool BN>
__global__ void post_kernel(const float* __restrict__ b,
                            const float* __restrict__ gamma, const float* __restrict__ beta,
                            const float* __restrict__ mean, const float* __restrict__ var,
                            float* __restrict__ out_ext, int n) {
    float* out = out_ext ? out_ext : g_C;
    long long idx = (long long)blockIdx.x * blockDim.x + threadIdx.x;
    if (idx >= (long long)n * C) return;
    int c = (int)(idx % C);
    float v = g_B[idx] + b[c];
    if (BN) {
        v = (v - mean[c]) * rsqrtf(var[c] + 1e-5f) * gamma[c] + beta[c];
        v = fmaxf(v, 0.0f);
    }
    out[idx] = v;
}

static inline int cdiv(long long a, long long b) { return (int)((a + b - 1) / b); }

extern "C" void kernel_launch(void* const* d_in, const int* in_sizes, int n_in,
                              void* d_out, int out_size) {
    const float* x      = (const float*)d_in[0];
    const int*   ei     = (const int*)d_in[1];      // edge_index delivered as int32 [2, E]
    const float* W0     = (const float*)d_in[2];
    const float* b0     = (const float*)d_in[3];
    const float* gamma0 = (const float*)d_in[4];
    const float* beta0  = (const float*)d_in[5];
    const float* mean0  = (const float*)d_in[6];
    const float* var0   = (const float*)d_in[7];
    const float* W1     = (const float*)d_in[8];
    const float* b1     = (const float*)d_in[9];
    const float* gamma1 = (const float*)d_in[10];
    const float* beta1  = (const float*)d_in[11];
    const float* mean1  = (const float*)d_in[12];
    const float* var1   = (const float*)d_in[13];
    const float* W2     = (const float*)d_in[14];
    const float* b2     = (const float*)d_in[15];
    float* out = (float*)d_out;

    const int n = in_sizes[0] / 128;   // 50000
    const int E = in_sizes[1] / 2;     // 800000
    const int* src = ei;
    const int* dst = ei + E;

    const int T = 256;

    // degrees + dinv
    zero_deg_kernel<<<cdiv(n, T), T>>>(n);
    count_deg_kernel<<<cdiv(E, T), T>>>(dst, E);
    dinv_kernel<<<cdiv(n, T), T>>>(n);

    // ---- layer 0: 128 -> 64, BN+ReLU ----
    {
        constexpr int K = 128, C = 64, TY = 4, RPT = 4, BR = TY * RPT;
        gemm_kernel<K, C, TY, RPT><<<cdiv(n, BR), dim3(C, TY)>>>(x, -1, W0, n);
        init_self_kernel<C><<<cdiv((long long)n * C / 4, T), T>>>(n);
        edge_aggregate_kernel<C><<<cdiv((long long)E * (C / 4), T), T>>>(src, dst, E);
        post_kernel<C, true><<<cdiv((long long)n * C, T), T>>>(b0, gamma0, beta0, mean0, var0, nullptr, n);
    }
    // ---- layer 1: 64 -> 64, BN+ReLU ----
    {
        constexpr int K = 64, C = 64, TY = 4, RPT = 4, BR = TY * RPT;
        gemm_kernel<K, C, TY, RPT><<<cdiv(n, BR), dim3(C, TY)>>>(nullptr, 2, W1, n);
        init_self_kernel<C><<<cdiv((long long)n * C / 4, T), T>>>(n);
        edge_aggregate_kernel<C><<<cdiv((long long)E * (C / 4), T), T>>>(src, dst, E);
        post_kernel<C, true><<<cdiv((long long)n * C, T), T>>>(b1, gamma1, beta1, mean1, var1, nullptr, n);
    }
    // ---- layer 2: 64 -> 40, bias only ----
    {
        constexpr int K = 64, C = 40, TY = 6, RPT = 4, BR = TY * RPT;
        gemm_kernel<K, C, TY, RPT><<<cdiv(n, BR), dim3(C, TY)>>>(nullptr, 2, W2, n);
        init_self_kernel<C><<<cdiv((long long)n * C / 4, T), T>>>(n);
        edge_aggregate_kernel<C><<<cdiv((long long)E * (C / 4), T), T>>>(src, dst, E);
        post_kernel<C, false><<<cdiv((long long)n * C, T), T>>>(b2, nullptr, nullptr, nullptr, nullptr, out, n);
    }
}

// round 4
// speedup vs baseline: 2.7202x; 2.7202x over previous
#include <cuda_runtime.h>
#include <cuda_bf16.h>
#include <cstdint>

#define N_MAX 50000
#define E_MAX 800000
#define HID 64
#define SCAN_B 512

// Scratch (device globals; only referenced from device code)
__device__ int   g_deg[N_MAX];
__device__ int   g_incl[N_MAX];
__device__ int   g_bsum[(N_MAX + SCAN_B - 1) / SCAN_B];
__device__ int   g_boff[(N_MAX + SCAN_B - 1) / SCAN_B];
__device__ int   g_rowptr[N_MAX + 1];
__device__ int   g_cursor[N_MAX];
__device__ float g_dinv[N_MAX];
__device__ int2  g_edge[E_MAX];                       // (src, norm bits) sorted by dst
__device__ __align__(16) float g_A[N_MAX * HID];      // GEMM output h
__device__ __align__(16) float g_C[N_MAX * HID];      // layer activation
__device__ __align__(16) float g_s[HID];              // fused BN scale
__device__ __align__(16) float g_t[HID];              // fused BN shift

// ---------------- degree / dinv ----------------
__global__ void zero_deg_kernel(int n) {
    int i = blockIdx.x * blockDim.x + threadIdx.x;
    if (i < n) g_deg[i] = 0;
}

__global__ void count_deg_kernel(const int* __restrict__ dst, int E) {
    int i = blockIdx.x * blockDim.x + threadIdx.x;
    if (i < E) atomicAdd(&g_deg[dst[i]], 1);
}

__global__ void dinv_kernel(int n) {
    int i = blockIdx.x * blockDim.x + threadIdx.x;
    if (i < n) g_dinv[i] = rsqrtf((float)g_deg[i] + 1.0f);  // +1 self loop
}

// ---------------- prefix scan (3 kernels) ----------------
__global__ void scan1_kernel(int n) {
    __shared__ int sh[SCAN_B];
    int gid = blockIdx.x * SCAN_B + threadIdx.x;
    int v = (gid < n) ? g_deg[gid] : 0;
    sh[threadIdx.x] = v;
    __syncthreads();
#pragma unroll
    for (int off = 1; off < SCAN_B; off <<= 1) {
        int t = (threadIdx.x >= off) ? sh[threadIdx.x - off] : 0;
        __syncthreads();
        sh[threadIdx.x] += t;
        __syncthreads();
    }
    if (gid < n) g_incl[gid] = sh[threadIdx.x];
    if (threadIdx.x == SCAN_B - 1) g_bsum[blockIdx.x] = sh[SCAN_B - 1];
}

__global__ void scan2_kernel(int nb) {
    if (threadIdx.x == 0) {       // nb ~ 98, serial is negligible
        int run = 0;
        for (int i = 0; i < nb; i++) { g_boff[i] = run; run += g_bsum[i]; }
    }
}

__global__ void scan3_kernel(int n, int E) {
    int gid = blockIdx.x * blockDim.x + threadIdx.x;
    if (gid < n) {
        int rp = g_incl[gid] - g_deg[gid] + g_boff[gid / SCAN_B];
        g_rowptr[gid] = rp;
        g_cursor[gid] = rp;
    }
    if (gid == 0) g_rowptr[n] = E;
}

// ---------------- edge scatter (build CSR with precomputed norm) ----------------
__global__ void scatter_kernel(const int* __restrict__ src, const int* __restrict__ dst, int E) {
    int e = blockIdx.x * blockDim.x + threadIdx.x;
    if (e >= E) return;
    int s = src[e], d = dst[e];
    int pos = atomicAdd(&g_cursor[d], 1);
    g_edge[pos] = make_int2(s, __float_as_int(g_dinv[s] * g_dinv[d]));
}

// ---------------- fused BN prep: v*s + t  (s=gamma*rsqrt(var+eps), t=(b-mean)*s+beta) ----------------
__global__ void bn_prep_kernel(const float* __restrict__ b, const float* __restrict__ gamma,
                               const float* __restrict__ beta, const float* __restrict__ mean,
                               const float* __restrict__ var, int C) {
    int c = threadIdx.x;
    if (c >= C) return;
    if (gamma) {
        float s = gamma[c] * rsqrtf(var[c] + 1e-5f);
        g_s[c] = s;
        g_t[c] = (b[c] - mean[c]) * s + beta[c];
    } else {
        g_s[c] = 1.0f;
        g_t[c] = b[c];
    }
}

// ---------------- GEMM: g_A[n,C] = X[n,K] @ W[K,C] ----------------
__device__ __forceinline__ float4 fma4(float a, float4 w, float4 acc) {
    acc.x = fmaf(a, w.x, acc.x);
    acc.y = fmaf(a, w.y, acc.y);
    acc.z = fmaf(a, w.z, acc.z);
    acc.w = fmaf(a, w.w, acc.w);
    return acc;
}

template<int K, int C, int TY, int RPT>
__global__ void gemm_kernel(const float* __restrict__ x_ext, const float* __restrict__ W, int n) {
    const float* X = x_ext ? x_ext : g_C;
    constexpr int C4 = C / 4;
    constexpr int K4 = K / 4;
    constexpr int BR = TY * RPT;
    __shared__ __align__(16) float4 Wsv[K * C4];
    __shared__ __align__(16) float4 Xsv[BR * K4];
    const int nth = C4 * TY;
    const int tid = threadIdx.y * C4 + threadIdx.x;

    const float4* Wv = (const float4*)W;
    for (int i = tid; i < K * C4; i += nth) Wsv[i] = Wv[i];

    const int rowBlock = blockIdx.x * BR;
    for (int i = tid; i < BR * K4; i += nth) {
        int r = i / K4, q = i % K4;
        int row = rowBlock + r;
        Xsv[i] = (row < n) ? *(const float4*)&X[(size_t)row * K + q * 4]
                           : make_float4(0.f, 0.f, 0.f, 0.f);
    }
    __syncthreads();

    const int tx = threadIdx.x;
    const int r0 = threadIdx.y * RPT;
    float4 acc[RPT];
#pragma unroll
    for (int r = 0; r < RPT; r++) acc[r] = make_float4(0.f, 0.f, 0.f, 0.f);

#pragma unroll 4
    for (int k = 0; k < K; k += 4) {
        float4 w0 = Wsv[(k + 0) * C4 + tx];
        float4 w1 = Wsv[(k + 1) * C4 + tx];
        float4 w2 = Wsv[(k + 2) * C4 + tx];
        float4 w3 = Wsv[(k + 3) * C4 + tx];
#pragma unroll
        for (int r = 0; r < RPT; r++) {
            float4 xv = Xsv[(r0 + r) * K4 + (k >> 2)];
            acc[r] = fma4(xv.x, w0, acc[r]);
            acc[r] = fma4(xv.y, w1, acc[r]);
            acc[r] = fma4(xv.z, w2, acc[r]);
            acc[r] = fma4(xv.w, w3, acc[r]);
        }
    }
#pragma unroll
    for (int r = 0; r < RPT; r++) {
        int row = rowBlock + r0 + r;
        if (row < n) *(float4*)&g_A[(size_t)row * C + tx * 4] = acc[r];
    }
}

// ---------------- fused aggregation + self-loop + bias/BN/ReLU ----------------
// out[d] = act( (dinv[d]^2 * h[d] + sum_in norm*h[src]) * s + t )
template<int C, bool RELU>
__global__ void agg_kernel(float* __restrict__ out_ext, int n) {
    constexpr int Q = C / 4;
    int node = blockIdx.x * blockDim.y + threadIdx.y;
    if (node >= n) return;
    int lane = threadIdx.x;

    const float4* h4 = (const float4*)g_A;
    float dv = g_dinv[node];
    float sn = dv * dv;
    float4 acc = h4[(size_t)node * Q + lane];
    acc.x *= sn; acc.y *= sn; acc.z *= sn; acc.w *= sn;

    int jb = g_rowptr[node], je = g_rowptr[node + 1];
    for (int j = jb; j < je; j++) {
        int2 ed = g_edge[j];
        float w = __int_as_float(ed.y);
        float4 hv = h4[(size_t)ed.x * Q + lane];
        acc.x = fmaf(hv.x, w, acc.x);
        acc.y = fmaf(hv.y, w, acc.y);
        acc.z = fmaf(hv.z, w, acc.z);
        acc.w = fmaf(hv.w, w, acc.w);
    }

    float4 s = ((const float4*)g_s)[lane];
    float4 t = ((const float4*)g_t)[lane];
    float4 o;
    o.x = fmaf(acc.x, s.x, t.x);
    o.y = fmaf(acc.y, s.y, t.y);
    o.z = fmaf(acc.z, s.z, t.z);
    o.w = fmaf(acc.w, s.w, t.w);
    if (RELU) {
        o.x = fmaxf(o.x, 0.f); o.y = fmaxf(o.y, 0.f);
        o.z = fmaxf(o.z, 0.f); o.w = fmaxf(o.w, 0.f);
    }
    float* out = out_ext ? out_ext : g_C;
    *(float4*)&out[(size_t)node * C + lane * 4] = o;
}

static inline int cdiv(long long a, long long b) { return (int)((a + b - 1) / b); }

extern "C" void kernel_launch(void* const* d_in, const int* in_sizes, int n_in,
                              void* d_out, int out_size) {
    const float* x      = (const float*)d_in[0];
    const int*   ei     = (const int*)d_in[1];      // int32 [2, E]
    const float* W0     = (const float*)d_in[2];
    const float* b0     = (const float*)d_in[3];
    const float* gamma0 = (const float*)d_in[4];
    const float* beta0  = (const float*)d_in[5];
    const float* mean0  = (const float*)d_in[6];
    const float* var0   = (const float*)d_in[7];
    const float* W1     = (const float*)d_in[8];
    const float* b1     = (const float*)d_in[9];
    const float* gamma1 = (const float*)d_in[10];
    const float* beta1  = (const float*)d_in[11];
    const float* mean1  = (const float*)d_in[12];
    const float* var1   = (const float*)d_in[13];
    const float* W2     = (const float*)d_in[14];
    const float* b2     = (const float*)d_in[15];
    float* out = (float*)d_out;

    const int n = in_sizes[0] / 128;   // 50000
    const int E = in_sizes[1] / 2;     // 800000
    const int* src = ei;
    const int* dst = ei + E;

    const int T = 256;
    const int nb = cdiv(n, SCAN_B);

    // ---- CSR build: degree, dinv, prefix scan, scatter ----
    zero_deg_kernel<<<cdiv(n, T), T>>>(n);
    count_deg_kernel<<<cdiv(E, T), T>>>(dst, E);
    dinv_kernel<<<cdiv(n, T), T>>>(n);
    scan1_kernel<<<nb, SCAN_B>>>(n);
    scan2_kernel<<<1, 32>>>(nb);
    scan3_kernel<<<cdiv(n, T), T>>>(n, E);
    scatter_kernel<<<cdiv(E, T), T>>>(src, dst, E);

    // ---- layer 0: 128 -> 64, BN+ReLU ----
    {
        constexpr int K = 128, C = 64, TY = 8, RPT = 4, BR = TY * RPT;
        bn_prep_kernel<<<1, C>>>(b0, gamma0, beta0, mean0, var0, C);
        gemm_kernel<K, C, TY, RPT><<<cdiv(n, BR), dim3(C / 4, TY)>>>(x, W0, n);
        agg_kernel<C, true><<<cdiv(n, 16), dim3(C / 4, 16)>>>(nullptr, n);
    }
    // ---- layer 1: 64 -> 64, BN+ReLU ----
    {
        constexpr int K = 64, C = 64, TY = 8, RPT = 4, BR = TY * RPT;
        bn_prep_kernel<<<1, C>>>(b1, gamma1, beta1, mean1, var1, C);
        gemm_kernel<K, C, TY, RPT><<<cdiv(n, BR), dim3(C / 4, TY)>>>(nullptr, W1, n);
        agg_kernel<C, true><<<cdiv(n, 16), dim3(C / 4, 16)>>>(nullptr, n);
    }
    // ---- layer 2: 64 -> 40, bias only ----
    {
        constexpr int K = 64, C = 40, TY = 16, RPT = 4, BR = TY * RPT;
        bn_prep_kernel<<<1, C>>>(b2, nullptr, nullptr, nullptr, nullptr, C);
        gemm_kernel<K, C, TY, RPT><<<cdiv(n, BR), dim3(C / 4, TY)>>>(nullptr, W2, n);
        agg_kernel<C, false><<<cdiv(n, 25), dim3(C / 4, 25)>>>(out, n);
    }
}